// round 6
// baseline (speedup 1.0000x reference)
#include <cuda_runtime.h>
#include <cuda_bf16.h>
#include <math.h>
#include <stdint.h>

#define S_DIM 4
#define B_DIM 4096
#define D_DIM 768
#define K_DIM 8192
#define N_ROWS 16384
#define ROWS_PER_CTA 32
#define TOT_ELEMS 134217728LL   // N_ROWS * K_DIM

#define KTOT 2304               // 3 * D_DIM (concatenated split planes)

// ---------------- scratch (device globals; no allocation allowed) ----------------
__device__ float g_logits[(size_t)N_ROWS * K_DIM];   // 512 MB
__device__ float g_inv_norm[N_ROWS];
__device__ float g_shift[S_DIM * K_DIM];
__device__ float g_c[S_DIM * K_DIM];
__device__ float g_A[S_DIM * K_DIM];
__device__ float g_r[N_ROWS];
__device__ float g_lse[N_ROWS];
__device__ float g_part_m[4 * S_DIM * K_DIM];
__device__ float g_part_s[4 * S_DIM * K_DIM];
__device__ float g_loss;

// concatenated bf16 split planes:  A3 = [Ah | Ah | Am],  B3 = [Bh | Bm | Bh]
__device__ __nv_bfloat16 g_A3[(size_t)N_ROWS * KTOT];   // 75.5 MB
__device__ __nv_bfloat16 g_B3[(size_t)K_DIM * KTOT];    // 37.7 MB

// ---------------- helpers ---------------------------------------------------------
__device__ __forceinline__ uint32_t smem_u32(const void* p) {
    uint32_t a;
    asm("{ .reg .u64 t; cvta.to.shared.u64 t, %1; cvt.u32.u64 %0, t; }" : "=r"(a) : "l"(p));
    return a;
}

#define CP_ASYNC16(s, g) \
    asm volatile("cp.async.cg.shared.global [%0], [%1], 16;" :: "r"(s), "l"(g) : "memory")
#define CP_COMMIT() asm volatile("cp.async.commit_group;" ::: "memory")
#define CP_WAIT1()  asm volatile("cp.async.wait_group 1;" ::: "memory")

#define LDMATRIX_X4(r0, r1, r2, r3, addr) \
    asm volatile("ldmatrix.sync.aligned.m8n8.x4.shared.b16 {%0,%1,%2,%3}, [%4];" \
        : "=r"(r0), "=r"(r1), "=r"(r2), "=r"(r3) : "r"(addr))

#define MMA_16816(c0, c1, c2, c3, a0, a1, a2, a3, b0, b1) \
    asm volatile("mma.sync.aligned.m16n8k16.row.col.f32.bf16.bf16.f32 " \
        "{%0,%1,%2,%3}, {%4,%5,%6,%7}, {%8,%9}, {%0,%1,%2,%3};" \
        : "+f"(c0), "+f"(c1), "+f"(c2), "+f"(c3) \
        : "r"(a0), "r"(a1), "r"(a2), "r"(a3), "r"(b0), "r"(b1))

// ---------------- fast exp on the FMA pipe (rel err ~1e-7 for x <= 50) ----------
__device__ __forceinline__ float fast_exp(float x) {
    float t = x * 1.4426950408889634f;
    t = fmaxf(t, -127.0f);
    float n = rintf(t);
    float f = t - n;
    float p = 1.5403530393381609e-4f;
    p = fmaf(p, f, 1.3333558146428443e-3f);
    p = fmaf(p, f, 9.6181291076284772e-3f);
    p = fmaf(p, f, 5.5504108664821580e-2f);
    p = fmaf(p, f, 2.4022650695910072e-1f);
    p = fmaf(p, f, 6.9314718055994531e-1f);
    p = fmaf(p, f, 1.0f);
    return __int_as_float(((int)n + 127) << 23) * p;
}

// ---------------- K0: row norms ---------------------------------------------------
__global__ void __launch_bounds__(256) norm_kernel(const float* __restrict__ X) {
    int row = blockIdx.x * 8 + (threadIdx.x >> 5);
    int lane = threadIdx.x & 31;
    const float* xr = X + (size_t)row * D_DIM;
    float ss = 0.f;
    for (int i = lane; i < D_DIM; i += 32) { float v = xr[i]; ss = fmaf(v, v, ss); }
    #pragma unroll
    for (int o = 16; o > 0; o >>= 1) ss += __shfl_xor_sync(0xffffffffu, ss, o);
    if (lane == 0) g_inv_norm[row] = 1.0f / fmaxf(sqrtf(ss), 1e-7f);
}

// ---------------- split converters ------------------------------------------------
__global__ void __launch_bounds__(256) convA_kernel(const float* __restrict__ X) {
    size_t g = (size_t)blockIdx.x * 256 + threadIdx.x;   // pair index
    int row = (int)(g / (D_DIM / 2));
    int c2 = (int)(g % (D_DIM / 2)) * 2;
    float sc = g_inv_norm[row];
    float2 v = *(const float2*)(X + (size_t)row * D_DIM + c2);
    float a0 = v.x * sc, a1 = v.y * sc;
    __nv_bfloat16 h0 = __float2bfloat16(a0);
    __nv_bfloat16 h1 = __float2bfloat16(a1);
    __nv_bfloat16 m0 = __float2bfloat16(a0 - __bfloat162float(h0));
    __nv_bfloat16 m1 = __float2bfloat16(a1 - __bfloat162float(h1));
    __nv_bfloat16* rowp = g_A3 + (size_t)row * KTOT;
    *(__nv_bfloat162*)(rowp + c2)             = __nv_bfloat162(h0, h1);
    *(__nv_bfloat162*)(rowp + D_DIM + c2)     = __nv_bfloat162(h0, h1);
    *(__nv_bfloat162*)(rowp + 2 * D_DIM + c2) = __nv_bfloat162(m0, m1);
}

__global__ void __launch_bounds__(256) convB_kernel(const float* __restrict__ Wm) {
    size_t g = (size_t)blockIdx.x * 256 + threadIdx.x;
    int row = (int)(g / (D_DIM / 2));
    int c2 = (int)(g % (D_DIM / 2)) * 2;
    float2 v = *(const float2*)(Wm + (size_t)row * D_DIM + c2);
    __nv_bfloat16 h0 = __float2bfloat16(v.x);
    __nv_bfloat16 h1 = __float2bfloat16(v.y);
    __nv_bfloat16 m0 = __float2bfloat16(v.x - __bfloat162float(h0));
    __nv_bfloat16 m1 = __float2bfloat16(v.y - __bfloat162float(h1));
    __nv_bfloat16* rowp = g_B3 + (size_t)row * KTOT;
    *(__nv_bfloat162*)(rowp + c2)             = __nv_bfloat162(h0, h1);
    *(__nv_bfloat162*)(rowp + D_DIM + c2)     = __nv_bfloat162(m0, m1);
    *(__nv_bfloat162*)(rowp + 2 * D_DIM + c2) = __nv_bfloat162(h0, h1);
}

// ---------------- K1: HMMA GEMM (bf16x2 split, K=2304, fp32 accum) ---------------
// CTA tile 128m x 256n, 8 warps of 64x64: 8 LDSM per 32 MMAs per k16-step.
#define BM 128
#define BN 256
#define BKK 32
#define NIT (KTOT / BKK)            // 72
#define STAGE_A (128 * 80)          // 10240 B
#define STAGE_B (256 * 80)          // 20480 B
#define STAGE_BYTES (STAGE_A + STAGE_B)   // 30720
#define NSTAGE 3
#define GEMM_SMEM (NSTAGE * STAGE_BYTES)  // 92160

__global__ void __launch_bounds__(256, 1) gemm_hmma(const __nv_bfloat16* __restrict__ A3,
                                                    const __nv_bfloat16* __restrict__ B3) {
    extern __shared__ char smem[];
    const uint32_t sbase = smem_u32(smem);
    const int tid = threadIdx.x;
    const int wid = tid >> 5, lid = tid & 31;
    const int bm = blockIdx.y * BM;
    const int bn = blockIdx.x * BN;
    const int wm = (wid & 1) * 64;      // 2 warps in m
    const int wn = (wid >> 1) * 64;     // 4 warps in n

    // cp.async mapping: A = 512 chunks (2/thread), B = 1024 chunks (4/thread)
    const int ra0 = (tid) >> 2,        ca0 = (tid) & 3;
    const int ra1 = (tid + 256) >> 2,  ca1 = (tid + 256) & 3;
    const __nv_bfloat16* gA0 = A3 + (size_t)(bm + ra0) * KTOT + ca0 * 8;
    const __nv_bfloat16* gA1 = A3 + (size_t)(bm + ra1) * KTOT + ca1 * 8;
    const uint32_t sAo0 = ra0 * 80 + ca0 * 16;
    const uint32_t sAo1 = ra1 * 80 + ca1 * 16;
    const __nv_bfloat16* gB[4];
    uint32_t sBo[4];
    #pragma unroll
    for (int i = 0; i < 4; i++) {
        const int ch = tid + i * 256;
        const int r = ch >> 2, c = ch & 3;
        gB[i] = B3 + (size_t)(bn + r) * KTOT + c * 8;
        sBo[i] = r * 80 + c * 16;
    }

    // ldmatrix per-thread addressing
    const int lrow = (lid & 7) + ((lid >> 3) & 1) * 8;   // row within 16-row block
    const int lkb = ((lid >> 4) & 1) * 16;               // 16B half within k16
    const uint32_t aoff = (uint32_t)(wm + lrow) * 80 + lkb;
    const uint32_t boff = (uint32_t)(wn + lrow) * 80 + lkb;

    float acc[4][8][4];
    #pragma unroll
    for (int i = 0; i < 4; i++)
        #pragma unroll
        for (int j = 0; j < 8; j++)
            #pragma unroll
            for (int q = 0; q < 4; q++) acc[i][j][q] = 0.f;

    // prologue: stages 0,1
    #pragma unroll
    for (int st = 0; st < 2; st++) {
        const int k0 = st * BKK;
        const uint32_t sa = sbase + st * STAGE_BYTES;
        const uint32_t sb = sa + STAGE_A;
        CP_ASYNC16(sa + sAo0, gA0 + k0);
        CP_ASYNC16(sa + sAo1, gA1 + k0);
        #pragma unroll
        for (int i = 0; i < 4; i++) CP_ASYNC16(sb + sBo[i], gB[i] + k0);
        CP_COMMIT();
    }

    int st = 0;
    for (int it = 0; it < NIT; it++) {
        CP_WAIT1();
        __syncthreads();

        // prefetch stage it+2
        if (it + 2 < NIT) {
            const int ps = (st + 2 >= NSTAGE) ? st + 2 - NSTAGE : st + 2;
            const int k0 = (it + 2) * BKK;
            const uint32_t sa = sbase + ps * STAGE_BYTES;
            const uint32_t sb = sa + STAGE_A;
            CP_ASYNC16(sa + sAo0, gA0 + k0);
            CP_ASYNC16(sa + sAo1, gA1 + k0);
            #pragma unroll
            for (int i = 0; i < 4; i++) CP_ASYNC16(sb + sBo[i], gB[i] + k0);
        }
        CP_COMMIT();

        const uint32_t sa = sbase + st * STAGE_BYTES;
        const uint32_t sb = sa + STAGE_A;
        #pragma unroll
        for (int ks = 0; ks < 2; ks++) {
            uint32_t a[4][4];
            #pragma unroll
            for (int mt = 0; mt < 4; mt++) {
                uint32_t ad = sa + aoff + mt * (16 * 80) + ks * 32;
                LDMATRIX_X4(a[mt][0], a[mt][1], a[mt][2], a[mt][3], ad);
            }
            uint32_t b[4][4];
            #pragma unroll
            for (int np = 0; np < 4; np++) {
                uint32_t bd = sb + boff + np * (16 * 80) + ks * 32;
                // B3 is [n][k] row-major: NON-trans ldmatrix -> exact B-frag layout
                LDMATRIX_X4(b[np][0], b[np][1], b[np][2], b[np][3], bd);
            }
            #pragma unroll
            for (int mt = 0; mt < 4; mt++) {
                #pragma unroll
                for (int nt = 0; nt < 8; nt++) {
                    const int np = nt >> 1, no = nt & 1;
                    MMA_16816(acc[mt][nt][0], acc[mt][nt][1], acc[mt][nt][2], acc[mt][nt][3],
                              a[mt][0], a[mt][1], a[mt][2], a[mt][3],
                              b[np][no], b[np][2 + no]);
                }
            }
        }
        st = (st + 1 == NSTAGE) ? 0 : st + 1;
    }

    // epilogue: accum -> g_logits
    const int mrow = lid >> 2;
    const int mcol = (lid & 3) * 2;
    #pragma unroll
    for (int mt = 0; mt < 4; mt++) {
        #pragma unroll
        for (int nt = 0; nt < 8; nt++) {
            const int row = bm + wm + mt * 16 + mrow;
            const int col = bn + wn + nt * 8 + mcol;
            float2 v01 = make_float2(acc[mt][nt][0], acc[mt][nt][1]);
            float2 v23 = make_float2(acc[mt][nt][2], acc[mt][nt][3]);
            *(float2*)(g_logits + (size_t)row * K_DIM + col) = v01;
            *(float2*)(g_logits + (size_t)(row + 8) * K_DIM + col) = v23;
        }
    }
}

// ---------------- K2: column pass -------------------------------------------------
__global__ void __launch_bounds__(256) colpass_kernel() {
    const int k = blockIdx.x * 256 + threadIdx.x;
    const int bc = blockIdx.y;
    const int s = blockIdx.z;
    const float* __restrict__ base =
        g_logits + ((size_t)(s * B_DIM + bc * 1024)) * K_DIM + k;
    float m = -1e30f, sum = 0.f;
    for (int b0 = 0; b0 < 1024; b0 += 8) {
        float v[8];
        #pragma unroll
        for (int j = 0; j < 8; j++) v[j] = base[(size_t)(b0 + j) * K_DIM] * 20.0f;
        #pragma unroll
        for (int j = 0; j < 8; j++) {
            if (v[j] <= m) sum += fast_exp(v[j] - m);
            else { sum = fmaf(sum, fast_exp(m - v[j]), 1.0f); m = v[j]; }
        }
    }
    const int pidx = (bc * S_DIM + s) * K_DIM + k;
    g_part_m[pidx] = m;
    g_part_s[pidx] = sum;
}

__global__ void __launch_bounds__(256) combine1_kernel() {
    const int idx = blockIdx.x * 256 + threadIdx.x;
    const int s = idx >> 13, k = idx & (K_DIM - 1);
    float m = -1e30f;
    #pragma unroll
    for (int bc = 0; bc < 4; bc++)
        m = fmaxf(m, g_part_m[(bc * S_DIM + s) * K_DIM + k]);
    float A = 0.f;
    #pragma unroll
    for (int bc = 0; bc < 4; bc++) {
        const int pi = (bc * S_DIM + s) * K_DIM + k;
        A = fmaf(g_part_s[pi], fast_exp(g_part_m[pi] - m), A);
    }
    float A1 = 5.1847055285870724e21f * A;   // * exp(50)
    g_shift[idx] = m;
    g_c[idx] = 1.0f / (A1 + 1e-8f);
    g_A[idx] = 0.f;
}

__global__ void __launch_bounds__(256) update_c_kernel() {
    const int idx = blockIdx.x * 256 + threadIdx.x;
    float c = g_c[idx], A = g_A[idx];
    g_c[idx] = c / (c * A + 1e-8f);
    g_A[idx] = 0.f;
    if (idx == 0) g_loss = 0.f;
}

// ---------------- row passes ------------------------------------------------------
template <int MODE>
__global__ void __launch_bounds__(256) rowpass_kernel(float* __restrict__ outp) {
    __shared__ float sA[8], sB[8], sC[8];
    __shared__ float bcast[1];
    const int tid = threadIdx.x;
    const int warp = tid >> 5, lane = tid & 31;
    const int r0 = blockIdx.x * ROWS_PER_CTA;
    const int s = r0 >> 12;
    const float* __restrict__ shiftv = g_shift + s * K_DIM;
    const float* __restrict__ cv = g_c + s * K_DIM;

    float accR[32];
    if (MODE != 3) {
        #pragma unroll
        for (int j = 0; j < 32; j++) accR[j] = 0.f;
    }
    float lossAcc = 0.f;
    float ebuf[32];

    for (int rr = 0; rr < ROWS_PER_CTA; rr++) {
        const int row = r0 + rr;
        const float* __restrict__ lrow = g_logits + (size_t)row * K_DIM;
        float sumB = 0.f, sumV = 0.f;
        float lm = -1e30f, ls = 0.f;
        #pragma unroll
        for (int j = 0; j < 32; j++) {
            const int k = tid + (j << 8);
            float l = lrow[k];
            float e = fast_exp(fmaf(l, 20.0f, 50.0f - shiftv[k]));
            float t = e * cv[k];
            sumB += t;
            if (MODE == 3) {
                ebuf[j] = t;
                sumV = fmaf(t, l * 8.3333333333333339f, sumV);
            } else {
                ebuf[j] = e;
            }
            if (MODE == 1) {
                float pp = l * 8.3333333333333339f;
                if (pp <= lm) ls += fast_exp(pp - lm);
                else { ls = fmaf(ls, fast_exp(lm - pp), 1.0f); lm = pp; }
            }
        }
        #pragma unroll
        for (int o = 16; o > 0; o >>= 1) {
            sumB += __shfl_xor_sync(0xffffffffu, sumB, o);
            if (MODE == 3) sumV += __shfl_xor_sync(0xffffffffu, sumV, o);
            if (MODE == 1) {
                float m2 = __shfl_xor_sync(0xffffffffu, lm, o);
                float s2 = __shfl_xor_sync(0xffffffffu, ls, o);
                float mm = fmaxf(lm, m2);
                ls = ls * fast_exp(lm - mm) + s2 * fast_exp(m2 - mm);
                lm = mm;
            }
        }
        if (lane == 0) {
            sA[warp] = sumB;
            if (MODE == 3) sB[warp] = sumV;
            if (MODE == 1) { sB[warp] = lm; sC[warp] = ls; }
        }
        __syncthreads();
        if (tid == 0) {
            float Bt = 0.f, Vt = 0.f, Mt = -1e30f, St = 0.f;
            #pragma unroll
            for (int w = 0; w < 8; w++) {
                Bt += sA[w];
                if (MODE == 3) Vt += sB[w];
                if (MODE == 1) {
                    float m2 = sB[w], s2 = sC[w];
                    float mm = fmaxf(Mt, m2);
                    St = St * fast_exp(Mt - mm) + s2 * fast_exp(m2 - mm);
                    Mt = mm;
                }
            }
            float rnew;
            if (MODE == 1) {
                rnew = 1.0f / (Bt + 1e-8f);
                g_r[row] = rnew;
                g_lse[row] = Mt + logf(St);
            } else {
                float rold = g_r[row];
                rnew = rold / (rold * Bt + 1e-8f);
                if (MODE == 2) g_r[row] = rnew;
                if (MODE == 3) lossAcc = fmaf(rnew, g_lse[row] * Bt - Vt, lossAcc);
            }
            bcast[0] = rnew;
        }
        __syncthreads();
        const float rnew = bcast[0];
        if (MODE == 3) {
            float* orow = outp + (size_t)row * K_DIM;
            #pragma unroll
            for (int j = 0; j < 32; j++) orow[tid + (j << 8)] = ebuf[j] * rnew;
        } else {
            #pragma unroll
            for (int j = 0; j < 32; j++) accR[j] = fmaf(ebuf[j], rnew, accR[j]);
        }
    }

    if (MODE != 3) {
        float* Ag = g_A + s * K_DIM;
        #pragma unroll
        for (int j = 0; j < 32; j++) atomicAdd(&Ag[tid + (j << 8)], accR[j]);
    } else {
        if (tid == 0) atomicAdd(&g_loss, lossAcc);
    }
}

__global__ void finalize_kernel(float* dst) {
    dst[0] = g_loss * (1.0f / 16384.0f);
}

// ---------------- launch ----------------------------------------------------------
extern "C" void kernel_launch(void* const* d_in, const int* in_sizes, int n_in,
                              void* d_out, int out_size) {
    const float* x = (const float*)d_in[0];
    const float* W = (const float*)d_in[1];
    if (n_in >= 2 && in_sizes[0] == K_DIM * D_DIM && in_sizes[1] == N_ROWS * D_DIM) {
        const float* t = x; x = W; W = t;
    }
    float* out = (float*)d_out;

    float* outp = out;
    if ((long long)out_size < TOT_ELEMS) {
        void* p = nullptr;
        cudaGetSymbolAddress(&p, g_logits);
        outp = (float*)p;
    }

    void *pA3, *pB3;
    cudaGetSymbolAddress(&pA3, g_A3);
    cudaGetSymbolAddress(&pB3, g_B3);

    cudaFuncSetAttribute(gemm_hmma, cudaFuncAttributeMaxDynamicSharedMemorySize, GEMM_SMEM);

    norm_kernel<<<N_ROWS / 8, 256>>>(x);
    convA_kernel<<<(N_ROWS * (D_DIM / 2)) / 256, 256>>>(x);
    convB_kernel<<<(K_DIM * (D_DIM / 2)) / 256, 256>>>(W);

    gemm_hmma<<<dim3(K_DIM / BN, N_ROWS / BM), 256, GEMM_SMEM>>>(
        (const __nv_bfloat16*)pA3, (const __nv_bfloat16*)pB3);

    colpass_kernel<<<dim3(K_DIM / 256, 4, S_DIM), 256>>>();
    combine1_kernel<<<(S_DIM * K_DIM) / 256, 256>>>();

    rowpass_kernel<1><<<N_ROWS / ROWS_PER_CTA, 256>>>(nullptr);
    update_c_kernel<<<(S_DIM * K_DIM) / 256, 256>>>();
    rowpass_kernel<2><<<N_ROWS / ROWS_PER_CTA, 256>>>(nullptr);
    update_c_kernel<<<(S_DIM * K_DIM) / 256, 256>>>();
    rowpass_kernel<3><<<N_ROWS / ROWS_PER_CTA, 256>>>(outp);

    if ((long long)out_size > TOT_ELEMS) {
        finalize_kernel<<<1, 1>>>(out + TOT_ELEMS);
    } else if (out_size == 1) {
        finalize_kernel<<<1, 1>>>(out);
    }
}

// round 7
// speedup vs baseline: 1.0858x; 1.0858x over previous
#include <cuda_runtime.h>
#include <cuda_bf16.h>
#include <math.h>
#include <stdint.h>

#define S_DIM 4
#define B_DIM 4096
#define D_DIM 768
#define K_DIM 8192
#define N_ROWS 16384
#define ROWS_PER_CTA 32
#define TOT_ELEMS 134217728LL   // N_ROWS * K_DIM

#define KTOT 2304               // 3 * D_DIM (concatenated split planes)

// ---------------- scratch (device globals; no allocation allowed) ----------------
__device__ float g_logits[(size_t)N_ROWS * K_DIM];   // 512 MB
__device__ float g_inv_norm[N_ROWS];
__device__ float g_shift[S_DIM * K_DIM];
__device__ float g_c[S_DIM * K_DIM];
__device__ float g_A[S_DIM * K_DIM];
__device__ float g_r[N_ROWS];
__device__ float g_lse[N_ROWS];
__device__ float g_part_m[4 * S_DIM * K_DIM];
__device__ float g_part_s[4 * S_DIM * K_DIM];
__device__ float g_loss;

// concatenated bf16 split planes:  A3 = [Ah | Ah | Am],  B3 = [Bh | Bm | Bh]
__device__ __nv_bfloat16 g_A3[(size_t)N_ROWS * KTOT];   // 75.5 MB
__device__ __nv_bfloat16 g_B3[(size_t)K_DIM * KTOT];    // 37.7 MB

// ---------------- helpers ---------------------------------------------------------
__device__ __forceinline__ uint32_t smem_u32(const void* p) {
    uint32_t a;
    asm("{ .reg .u64 t; cvta.to.shared.u64 t, %1; cvt.u32.u64 %0, t; }" : "=r"(a) : "l"(p));
    return a;
}

#define CP_ASYNC16(s, g) \
    asm volatile("cp.async.cg.shared.global [%0], [%1], 16;" :: "r"(s), "l"(g) : "memory")
#define CP_COMMIT() asm volatile("cp.async.commit_group;" ::: "memory")
#define CP_WAIT1()  asm volatile("cp.async.wait_group 1;" ::: "memory")

#define LDMATRIX_X4(r0, r1, r2, r3, addr) \
    asm volatile("ldmatrix.sync.aligned.m8n8.x4.shared.b16 {%0,%1,%2,%3}, [%4];" \
        : "=r"(r0), "=r"(r1), "=r"(r2), "=r"(r3) : "r"(addr))

#define MMA_16816(c0, c1, c2, c3, a0, a1, a2, a3, b0, b1) \
    asm volatile("mma.sync.aligned.m16n8k16.row.col.f32.bf16.bf16.f32 " \
        "{%0,%1,%2,%3}, {%4,%5,%6,%7}, {%8,%9}, {%0,%1,%2,%3};" \
        : "+f"(c0), "+f"(c1), "+f"(c2), "+f"(c3) \
        : "r"(a0), "r"(a1), "r"(a2), "r"(a3), "r"(b0), "r"(b1))

// ---------------- fast exp on the FMA pipe (rel err ~1e-7 for x <= 50) ----------
__device__ __forceinline__ float fast_exp(float x) {
    float t = x * 1.4426950408889634f;
    t = fmaxf(t, -127.0f);
    float n = rintf(t);
    float f = t - n;
    float p = 1.5403530393381609e-4f;
    p = fmaf(p, f, 1.3333558146428443e-3f);
    p = fmaf(p, f, 9.6181291076284772e-3f);
    p = fmaf(p, f, 5.5504108664821580e-2f);
    p = fmaf(p, f, 2.4022650695910072e-1f);
    p = fmaf(p, f, 6.9314718055994531e-1f);
    p = fmaf(p, f, 1.0f);
    return __int_as_float(((int)n + 127) << 23) * p;
}

// ---------------- K0: row norms ---------------------------------------------------
__global__ void __launch_bounds__(256) norm_kernel(const float* __restrict__ X) {
    int row = blockIdx.x * 8 + (threadIdx.x >> 5);
    int lane = threadIdx.x & 31;
    const float* xr = X + (size_t)row * D_DIM;
    float ss = 0.f;
    for (int i = lane; i < D_DIM; i += 32) { float v = xr[i]; ss = fmaf(v, v, ss); }
    #pragma unroll
    for (int o = 16; o > 0; o >>= 1) ss += __shfl_xor_sync(0xffffffffu, ss, o);
    if (lane == 0) g_inv_norm[row] = 1.0f / fmaxf(sqrtf(ss), 1e-7f);
}

// ---------------- split converters ------------------------------------------------
__global__ void __launch_bounds__(256) convA_kernel(const float* __restrict__ X) {
    size_t g = (size_t)blockIdx.x * 256 + threadIdx.x;   // pair index
    int row = (int)(g / (D_DIM / 2));
    int c2 = (int)(g % (D_DIM / 2)) * 2;
    float sc = g_inv_norm[row];
    float2 v = *(const float2*)(X + (size_t)row * D_DIM + c2);
    float a0 = v.x * sc, a1 = v.y * sc;
    __nv_bfloat16 h0 = __float2bfloat16(a0);
    __nv_bfloat16 h1 = __float2bfloat16(a1);
    __nv_bfloat16 m0 = __float2bfloat16(a0 - __bfloat162float(h0));
    __nv_bfloat16 m1 = __float2bfloat16(a1 - __bfloat162float(h1));
    __nv_bfloat16* rowp = g_A3 + (size_t)row * KTOT;
    *(__nv_bfloat162*)(rowp + c2)             = __nv_bfloat162(h0, h1);
    *(__nv_bfloat162*)(rowp + D_DIM + c2)     = __nv_bfloat162(h0, h1);
    *(__nv_bfloat162*)(rowp + 2 * D_DIM + c2) = __nv_bfloat162(m0, m1);
}

__global__ void __launch_bounds__(256) convB_kernel(const float* __restrict__ Wm) {
    size_t g = (size_t)blockIdx.x * 256 + threadIdx.x;
    int row = (int)(g / (D_DIM / 2));
    int c2 = (int)(g % (D_DIM / 2)) * 2;
    float2 v = *(const float2*)(Wm + (size_t)row * D_DIM + c2);
    __nv_bfloat16 h0 = __float2bfloat16(v.x);
    __nv_bfloat16 h1 = __float2bfloat16(v.y);
    __nv_bfloat16 m0 = __float2bfloat16(v.x - __bfloat162float(h0));
    __nv_bfloat16 m1 = __float2bfloat16(v.y - __bfloat162float(h1));
    __nv_bfloat16* rowp = g_B3 + (size_t)row * KTOT;
    *(__nv_bfloat162*)(rowp + c2)             = __nv_bfloat162(h0, h1);
    *(__nv_bfloat162*)(rowp + D_DIM + c2)     = __nv_bfloat162(m0, m1);
    *(__nv_bfloat162*)(rowp + 2 * D_DIM + c2) = __nv_bfloat162(h0, h1);
}

// ---------------- K1: HMMA GEMM (bf16x2 split, K=2304, fp32 accum) ---------------
// 128x128 CTA, 8 warps of 64x32 (R5 shape, 2 CTA/SM), BKK=64: half the barriers.
#define BM 128
#define BN 128
#define BKK 64
#define NIT (KTOT / BKK)            // 36
#define RSTR 144                    // padded row: 128B + 16B ((9r+c)%8 permutation)
#define STAGE_HALF (128 * RSTR)     // 18432 B per matrix per stage
#define STAGE_BYTES (2 * STAGE_HALF)   // 36864
#define NSTAGE 3
#define GEMM_SMEM (NSTAGE * STAGE_BYTES)   // 110592 (2 CTA/SM: 221184 <= 228KB)

__global__ void __launch_bounds__(256, 2) gemm_hmma(const __nv_bfloat16* __restrict__ A3,
                                                    const __nv_bfloat16* __restrict__ B3) {
    extern __shared__ char smem[];
    const uint32_t sbase = smem_u32(smem);
    const int tid = threadIdx.x;
    const int wid = tid >> 5, lid = tid & 31;
    const int bm = blockIdx.y * BM;
    const int bn = blockIdx.x * BN;
    const int wm = (wid & 1) * 64;      // 2 warps in m
    const int wn = (wid >> 1) * 32;     // 4 warps in n

    // cp.async mapping: 1024 16B-chunks per matrix per stage, 4 per thread each.
    // chunk ch: r = ch>>3 (0..127), c = ch&7 (16B col)
    const __nv_bfloat16* gA[4];
    const __nv_bfloat16* gB[4];
    uint32_t so[4];
    #pragma unroll
    for (int i = 0; i < 4; i++) {
        const int ch = tid + i * 256;
        const int r = ch >> 3, c = ch & 7;
        gA[i] = A3 + (size_t)(bm + r) * KTOT + c * 8;
        gB[i] = B3 + (size_t)(bn + r) * KTOT + c * 8;
        so[i] = r * RSTR + c * 16;
    }

    // ldmatrix per-thread addressing
    const int lrow = (lid & 7) + ((lid >> 3) & 1) * 8;   // row within 16-row block
    const int lkb = ((lid >> 4) & 1) * 16;               // 16B half within k16
    const uint32_t aoff = (uint32_t)(wm + lrow) * RSTR + lkb;
    const uint32_t boff = (uint32_t)(wn + lrow) * RSTR + lkb;

    float acc[4][4][4];
    #pragma unroll
    for (int i = 0; i < 4; i++)
        #pragma unroll
        for (int j = 0; j < 4; j++)
            #pragma unroll
            for (int q = 0; q < 4; q++) acc[i][j][q] = 0.f;

    // prologue: stages 0,1
    #pragma unroll
    for (int st = 0; st < 2; st++) {
        const int k0 = st * BKK;
        const uint32_t sa = sbase + st * STAGE_BYTES;
        const uint32_t sb = sa + STAGE_HALF;
        #pragma unroll
        for (int i = 0; i < 4; i++) {
            CP_ASYNC16(sa + so[i], gA[i] + k0);
            CP_ASYNC16(sb + so[i], gB[i] + k0);
        }
        CP_COMMIT();
    }

    int st = 0;
    for (int it = 0; it < NIT; it++) {
        CP_WAIT1();
        __syncthreads();

        // prefetch stage it+2
        if (it + 2 < NIT) {
            const int ps = (st + 2 >= NSTAGE) ? st + 2 - NSTAGE : st + 2;
            const int k0 = (it + 2) * BKK;
            const uint32_t sa = sbase + ps * STAGE_BYTES;
            const uint32_t sb = sa + STAGE_HALF;
            #pragma unroll
            for (int i = 0; i < 4; i++) {
                CP_ASYNC16(sa + so[i], gA[i] + k0);
                CP_ASYNC16(sb + so[i], gB[i] + k0);
            }
        }
        CP_COMMIT();

        const uint32_t sa = sbase + st * STAGE_BYTES;
        const uint32_t sb = sa + STAGE_HALF;
        #pragma unroll
        for (int ks = 0; ks < 4; ks++) {
            uint32_t a[4][4];
            #pragma unroll
            for (int mt = 0; mt < 4; mt++) {
                uint32_t ad = sa + aoff + mt * (16 * RSTR) + ks * 32;
                LDMATRIX_X4(a[mt][0], a[mt][1], a[mt][2], a[mt][3], ad);
            }
            uint32_t b[2][4];
            #pragma unroll
            for (int np = 0; np < 2; np++) {
                uint32_t bd = sb + boff + np * (16 * RSTR) + ks * 32;
                // B3 is [n][k] row-major: NON-trans ldmatrix -> exact B-frag layout
                LDMATRIX_X4(b[np][0], b[np][1], b[np][2], b[np][3], bd);
            }
            #pragma unroll
            for (int mt = 0; mt < 4; mt++) {
                #pragma unroll
                for (int nt = 0; nt < 4; nt++) {
                    const int np = nt >> 1, no = nt & 1;
                    MMA_16816(acc[mt][nt][0], acc[mt][nt][1], acc[mt][nt][2], acc[mt][nt][3],
                              a[mt][0], a[mt][1], a[mt][2], a[mt][3],
                              b[np][no], b[np][2 + no]);
                }
            }
        }
        st = (st + 1 == NSTAGE) ? 0 : st + 1;
    }

    // epilogue: accum -> g_logits
    const int mrow = lid >> 2;
    const int mcol = (lid & 3) * 2;
    #pragma unroll
    for (int mt = 0; mt < 4; mt++) {
        #pragma unroll
        for (int nt = 0; nt < 4; nt++) {
            const int row = bm + wm + mt * 16 + mrow;
            const int col = bn + wn + nt * 8 + mcol;
            float2 v01 = make_float2(acc[mt][nt][0], acc[mt][nt][1]);
            float2 v23 = make_float2(acc[mt][nt][2], acc[mt][nt][3]);
            *(float2*)(g_logits + (size_t)row * K_DIM + col) = v01;
            *(float2*)(g_logits + (size_t)(row + 8) * K_DIM + col) = v23;
        }
    }
}

// ---------------- K2: column pass -------------------------------------------------
__global__ void __launch_bounds__(256) colpass_kernel() {
    const int k = blockIdx.x * 256 + threadIdx.x;
    const int bc = blockIdx.y;
    const int s = blockIdx.z;
    const float* __restrict__ base =
        g_logits + ((size_t)(s * B_DIM + bc * 1024)) * K_DIM + k;
    float m = -1e30f, sum = 0.f;
    for (int b0 = 0; b0 < 1024; b0 += 8) {
        float v[8];
        #pragma unroll
        for (int j = 0; j < 8; j++) v[j] = base[(size_t)(b0 + j) * K_DIM] * 20.0f;
        #pragma unroll
        for (int j = 0; j < 8; j++) {
            if (v[j] <= m) sum += fast_exp(v[j] - m);
            else { sum = fmaf(sum, fast_exp(m - v[j]), 1.0f); m = v[j]; }
        }
    }
    const int pidx = (bc * S_DIM + s) * K_DIM + k;
    g_part_m[pidx] = m;
    g_part_s[pidx] = sum;
}

__global__ void __launch_bounds__(256) combine1_kernel() {
    const int idx = blockIdx.x * 256 + threadIdx.x;
    const int s = idx >> 13, k = idx & (K_DIM - 1);
    float m = -1e30f;
    #pragma unroll
    for (int bc = 0; bc < 4; bc++)
        m = fmaxf(m, g_part_m[(bc * S_DIM + s) * K_DIM + k]);
    float A = 0.f;
    #pragma unroll
    for (int bc = 0; bc < 4; bc++) {
        const int pi = (bc * S_DIM + s) * K_DIM + k;
        A = fmaf(g_part_s[pi], fast_exp(g_part_m[pi] - m), A);
    }
    float A1 = 5.1847055285870724e21f * A;   // * exp(50)
    g_shift[idx] = m;
    g_c[idx] = 1.0f / (A1 + 1e-8f);
    g_A[idx] = 0.f;
}

__global__ void __launch_bounds__(256) update_c_kernel() {
    const int idx = blockIdx.x * 256 + threadIdx.x;
    float c = g_c[idx], A = g_A[idx];
    g_c[idx] = c / (c * A + 1e-8f);
    g_A[idx] = 0.f;
    if (idx == 0) g_loss = 0.f;
}

// ---------------- row passes ------------------------------------------------------
template <int MODE>
__global__ void __launch_bounds__(256) rowpass_kernel(float* __restrict__ outp) {
    __shared__ float sA[8], sB[8], sC[8];
    __shared__ float bcast[1];
    const int tid = threadIdx.x;
    const int warp = tid >> 5, lane = tid & 31;
    const int r0 = blockIdx.x * ROWS_PER_CTA;
    const int s = r0 >> 12;
    const float* __restrict__ shiftv = g_shift + s * K_DIM;
    const float* __restrict__ cv = g_c + s * K_DIM;

    float accR[32];
    if (MODE != 3) {
        #pragma unroll
        for (int j = 0; j < 32; j++) accR[j] = 0.f;
    }
    float lossAcc = 0.f;
    float ebuf[32];

    for (int rr = 0; rr < ROWS_PER_CTA; rr++) {
        const int row = r0 + rr;
        const float* __restrict__ lrow = g_logits + (size_t)row * K_DIM;
        float sumB = 0.f, sumV = 0.f;
        float lm = -1e30f, ls = 0.f;
        #pragma unroll
        for (int j = 0; j < 32; j++) {
            const int k = tid + (j << 8);
            float l = lrow[k];
            float e = fast_exp(fmaf(l, 20.0f, 50.0f - shiftv[k]));
            float t = e * cv[k];
            sumB += t;
            if (MODE == 3) {
                ebuf[j] = t;
                sumV = fmaf(t, l * 8.3333333333333339f, sumV);
            } else {
                ebuf[j] = e;
            }
            if (MODE == 1) {
                float pp = l * 8.3333333333333339f;
                if (pp <= lm) ls += fast_exp(pp - lm);
                else { ls = fmaf(ls, fast_exp(lm - pp), 1.0f); lm = pp; }
            }
        }
        #pragma unroll
        for (int o = 16; o > 0; o >>= 1) {
            sumB += __shfl_xor_sync(0xffffffffu, sumB, o);
            if (MODE == 3) sumV += __shfl_xor_sync(0xffffffffu, sumV, o);
            if (MODE == 1) {
                float m2 = __shfl_xor_sync(0xffffffffu, lm, o);
                float s2 = __shfl_xor_sync(0xffffffffu, ls, o);
                float mm = fmaxf(lm, m2);
                ls = ls * fast_exp(lm - mm) + s2 * fast_exp(m2 - mm);
                lm = mm;
            }
        }
        if (lane == 0) {
            sA[warp] = sumB;
            if (MODE == 3) sB[warp] = sumV;
            if (MODE == 1) { sB[warp] = lm; sC[warp] = ls; }
        }
        __syncthreads();
        if (tid == 0) {
            float Bt = 0.f, Vt = 0.f, Mt = -1e30f, St = 0.f;
            #pragma unroll
            for (int w = 0; w < 8; w++) {
                Bt += sA[w];
                if (MODE == 3) Vt += sB[w];
                if (MODE == 1) {
                    float m2 = sB[w], s2 = sC[w];
                    float mm = fmaxf(Mt, m2);
                    St = St * fast_exp(Mt - mm) + s2 * fast_exp(m2 - mm);
                    Mt = mm;
                }
            }
            float rnew;
            if (MODE == 1) {
                rnew = 1.0f / (Bt + 1e-8f);
                g_r[row] = rnew;
                g_lse[row] = Mt + logf(St);
            } else {
                float rold = g_r[row];
                rnew = rold / (rold * Bt + 1e-8f);
                if (MODE == 2) g_r[row] = rnew;
                if (MODE == 3) lossAcc = fmaf(rnew, g_lse[row] * Bt - Vt, lossAcc);
            }
            bcast[0] = rnew;
        }
        __syncthreads();
        const float rnew = bcast[0];
        if (MODE == 3) {
            float* orow = outp + (size_t)row * K_DIM;
            #pragma unroll
            for (int j = 0; j < 32; j++) orow[tid + (j << 8)] = ebuf[j] * rnew;
        } else {
            #pragma unroll
            for (int j = 0; j < 32; j++) accR[j] = fmaf(ebuf[j], rnew, accR[j]);
        }
    }

    if (MODE != 3) {
        float* Ag = g_A + s * K_DIM;
        #pragma unroll
        for (int j = 0; j < 32; j++) atomicAdd(&Ag[tid + (j << 8)], accR[j]);
    } else {
        if (tid == 0) atomicAdd(&g_loss, lossAcc);
    }
}

__global__ void finalize_kernel(float* dst) {
    dst[0] = g_loss * (1.0f / 16384.0f);
}

// ---------------- launch ----------------------------------------------------------
extern "C" void kernel_launch(void* const* d_in, const int* in_sizes, int n_in,
                              void* d_out, int out_size) {
    const float* x = (const float*)d_in[0];
    const float* W = (const float*)d_in[1];
    if (n_in >= 2 && in_sizes[0] == K_DIM * D_DIM && in_sizes[1] == N_ROWS * D_DIM) {
        const float* t = x; x = W; W = t;
    }
    float* out = (float*)d_out;

    float* outp = out;
    if ((long long)out_size < TOT_ELEMS) {
        void* p = nullptr;
        cudaGetSymbolAddress(&p, g_logits);
        outp = (float*)p;
    }

    void *pA3, *pB3;
    cudaGetSymbolAddress(&pA3, g_A3);
    cudaGetSymbolAddress(&pB3, g_B3);

    cudaFuncSetAttribute(gemm_hmma, cudaFuncAttributeMaxDynamicSharedMemorySize, GEMM_SMEM);

    norm_kernel<<<N_ROWS / 8, 256>>>(x);
    convA_kernel<<<(N_ROWS * (D_DIM / 2)) / 256, 256>>>(x);
    convB_kernel<<<(K_DIM * (D_DIM / 2)) / 256, 256>>>(W);

    gemm_hmma<<<dim3(K_DIM / BN, N_ROWS / BM), 256, GEMM_SMEM>>>(
        (const __nv_bfloat16*)pA3, (const __nv_bfloat16*)pB3);

    colpass_kernel<<<dim3(K_DIM / 256, 4, S_DIM), 256>>>();
    combine1_kernel<<<(S_DIM * K_DIM) / 256, 256>>>();

    rowpass_kernel<1><<<N_ROWS / ROWS_PER_CTA, 256>>>(nullptr);
    update_c_kernel<<<(S_DIM * K_DIM) / 256, 256>>>();
    rowpass_kernel<2><<<N_ROWS / ROWS_PER_CTA, 256>>>(nullptr);
    update_c_kernel<<<(S_DIM * K_DIM) / 256, 256>>>();
    rowpass_kernel<3><<<N_ROWS / ROWS_PER_CTA, 256>>>(outp);

    if ((long long)out_size > TOT_ELEMS) {
        finalize_kernel<<<1, 1>>>(out + TOT_ELEMS);
    } else if (out_size == 1) {
        finalize_kernel<<<1, 1>>>(out);
    }
}

// round 8
// speedup vs baseline: 1.2415x; 1.1434x over previous
#include <cuda_runtime.h>
#include <cuda_bf16.h>
#include <math.h>
#include <stdint.h>

#define S_DIM 4
#define B_DIM 4096
#define D_DIM 768
#define K_DIM 8192
#define N_ROWS 16384
#define RPC 16                  // rows per CTA in row passes
#define TOT_ELEMS 134217728LL   // N_ROWS * K_DIM

#define KTOT 2304               // 3 * D_DIM (concatenated split planes)

// ---------------- scratch (device globals; no allocation allowed) ----------------
__device__ float g_logits[(size_t)N_ROWS * K_DIM];   // 512 MB
__device__ float g_inv_norm[N_ROWS];
__device__ float g_shift[S_DIM * K_DIM];
__device__ float g_c[S_DIM * K_DIM];
__device__ float g_A[S_DIM * K_DIM];
__device__ float g_r[N_ROWS];
__device__ float g_lse[N_ROWS];
__device__ float g_part_m[4 * S_DIM * K_DIM];
__device__ float g_part_s[4 * S_DIM * K_DIM];
__device__ float g_loss;

// concatenated bf16 split planes:  A3 = [Ah | Ah | Am],  B3 = [Bh | Bm | Bh]
__device__ __nv_bfloat16 g_A3[(size_t)N_ROWS * KTOT];   // 75.5 MB
__device__ __nv_bfloat16 g_B3[(size_t)K_DIM * KTOT];    // 37.7 MB

// ---------------- helpers ---------------------------------------------------------
__device__ __forceinline__ uint32_t smem_u32(const void* p) {
    uint32_t a;
    asm("{ .reg .u64 t; cvta.to.shared.u64 t, %1; cvt.u32.u64 %0, t; }" : "=r"(a) : "l"(p));
    return a;
}

#define CP_ASYNC16(s, g) \
    asm volatile("cp.async.cg.shared.global [%0], [%1], 16;" :: "r"(s), "l"(g) : "memory")
#define CP_COMMIT() asm volatile("cp.async.commit_group;" ::: "memory")
#define CP_WAIT1()  asm volatile("cp.async.wait_group 1;" ::: "memory")

#define LDMATRIX_X4(r0, r1, r2, r3, addr) \
    asm volatile("ldmatrix.sync.aligned.m8n8.x4.shared.b16 {%0,%1,%2,%3}, [%4];" \
        : "=r"(r0), "=r"(r1), "=r"(r2), "=r"(r3) : "r"(addr))

#define MMA_16816(c0, c1, c2, c3, a0, a1, a2, a3, b0, b1) \
    asm volatile("mma.sync.aligned.m16n8k16.row.col.f32.bf16.bf16.f32 " \
        "{%0,%1,%2,%3}, {%4,%5,%6,%7}, {%8,%9}, {%0,%1,%2,%3};" \
        : "+f"(c0), "+f"(c1), "+f"(c2), "+f"(c3) \
        : "r"(a0), "r"(a1), "r"(a2), "r"(a3), "r"(b0), "r"(b1))

// ---------------- fast exp on the FMA pipe (rel err ~1e-7 for x <= 50) ----------
__device__ __forceinline__ float fast_exp(float x) {
    float t = x * 1.4426950408889634f;
    t = fmaxf(t, -127.0f);
    float n = rintf(t);
    float f = t - n;
    float p = 1.5403530393381609e-4f;
    p = fmaf(p, f, 1.3333558146428443e-3f);
    p = fmaf(p, f, 9.6181291076284772e-3f);
    p = fmaf(p, f, 5.5504108664821580e-2f);
    p = fmaf(p, f, 2.4022650695910072e-1f);
    p = fmaf(p, f, 6.9314718055994531e-1f);
    p = fmaf(p, f, 1.0f);
    return __int_as_float(((int)n + 127) << 23) * p;
}

// ---------------- K0: row norms ---------------------------------------------------
__global__ void __launch_bounds__(256) norm_kernel(const float* __restrict__ X) {
    int row = blockIdx.x * 8 + (threadIdx.x >> 5);
    int lane = threadIdx.x & 31;
    const float* xr = X + (size_t)row * D_DIM;
    float ss = 0.f;
    for (int i = lane; i < D_DIM; i += 32) { float v = xr[i]; ss = fmaf(v, v, ss); }
    #pragma unroll
    for (int o = 16; o > 0; o >>= 1) ss += __shfl_xor_sync(0xffffffffu, ss, o);
    if (lane == 0) g_inv_norm[row] = 1.0f / fmaxf(sqrtf(ss), 1e-7f);
}

// ---------------- split converters ------------------------------------------------
__global__ void __launch_bounds__(256) convA_kernel(const float* __restrict__ X) {
    size_t g = (size_t)blockIdx.x * 256 + threadIdx.x;   // pair index
    int row = (int)(g / (D_DIM / 2));
    int c2 = (int)(g % (D_DIM / 2)) * 2;
    float sc = g_inv_norm[row];
    float2 v = *(const float2*)(X + (size_t)row * D_DIM + c2);
    float a0 = v.x * sc, a1 = v.y * sc;
    __nv_bfloat16 h0 = __float2bfloat16(a0);
    __nv_bfloat16 h1 = __float2bfloat16(a1);
    __nv_bfloat16 m0 = __float2bfloat16(a0 - __bfloat162float(h0));
    __nv_bfloat16 m1 = __float2bfloat16(a1 - __bfloat162float(h1));
    __nv_bfloat16* rowp = g_A3 + (size_t)row * KTOT;
    *(__nv_bfloat162*)(rowp + c2)             = __nv_bfloat162(h0, h1);
    *(__nv_bfloat162*)(rowp + D_DIM + c2)     = __nv_bfloat162(h0, h1);
    *(__nv_bfloat162*)(rowp + 2 * D_DIM + c2) = __nv_bfloat162(m0, m1);
}

__global__ void __launch_bounds__(256) convB_kernel(const float* __restrict__ Wm) {
    size_t g = (size_t)blockIdx.x * 256 + threadIdx.x;
    int row = (int)(g / (D_DIM / 2));
    int c2 = (int)(g % (D_DIM / 2)) * 2;
    float2 v = *(const float2*)(Wm + (size_t)row * D_DIM + c2);
    __nv_bfloat16 h0 = __float2bfloat16(v.x);
    __nv_bfloat16 h1 = __float2bfloat16(v.y);
    __nv_bfloat16 m0 = __float2bfloat16(v.x - __bfloat162float(h0));
    __nv_bfloat16 m1 = __float2bfloat16(v.y - __bfloat162float(h1));
    __nv_bfloat16* rowp = g_B3 + (size_t)row * KTOT;
    *(__nv_bfloat162*)(rowp + c2)             = __nv_bfloat162(h0, h1);
    *(__nv_bfloat162*)(rowp + D_DIM + c2)     = __nv_bfloat162(m0, m1);
    *(__nv_bfloat162*)(rowp + 2 * D_DIM + c2) = __nv_bfloat162(h0, h1);
}

// ---------------- K1: HMMA GEMM (bf16x2 split, K=2304, fp32 accum) ---------------
// 128x128 CTA, 8 warps of 64x32, 2 CTA/SM, BKK=64 (R7 best shape).
#define BM 128
#define BN 128
#define BKK 64
#define NIT (KTOT / BKK)            // 36
#define RSTR 144                    // padded row: 128B + 16B ((9r+c)%8 permutation)
#define STAGE_HALF (128 * RSTR)     // 18432 B per matrix per stage
#define STAGE_BYTES (2 * STAGE_HALF)   // 36864
#define NSTAGE 3
#define GEMM_SMEM (NSTAGE * STAGE_BYTES)   // 110592 (2 CTA/SM)

__global__ void __launch_bounds__(256, 2) gemm_hmma(const __nv_bfloat16* __restrict__ A3,
                                                    const __nv_bfloat16* __restrict__ B3) {
    extern __shared__ char smem[];
    const uint32_t sbase = smem_u32(smem);
    const int tid = threadIdx.x;
    const int wid = tid >> 5, lid = tid & 31;
    const int bm = blockIdx.y * BM;
    const int bn = blockIdx.x * BN;
    const int wm = (wid & 1) * 64;      // 2 warps in m
    const int wn = (wid >> 1) * 32;     // 4 warps in n

    const __nv_bfloat16* gA[4];
    const __nv_bfloat16* gB[4];
    uint32_t so[4];
    #pragma unroll
    for (int i = 0; i < 4; i++) {
        const int ch = tid + i * 256;
        const int r = ch >> 3, c = ch & 7;
        gA[i] = A3 + (size_t)(bm + r) * KTOT + c * 8;
        gB[i] = B3 + (size_t)(bn + r) * KTOT + c * 8;
        so[i] = r * RSTR + c * 16;
    }

    const int lrow = (lid & 7) + ((lid >> 3) & 1) * 8;
    const int lkb = ((lid >> 4) & 1) * 16;
    const uint32_t aoff = (uint32_t)(wm + lrow) * RSTR + lkb;
    const uint32_t boff = (uint32_t)(wn + lrow) * RSTR + lkb;

    float acc[4][4][4];
    #pragma unroll
    for (int i = 0; i < 4; i++)
        #pragma unroll
        for (int j = 0; j < 4; j++)
            #pragma unroll
            for (int q = 0; q < 4; q++) acc[i][j][q] = 0.f;

    #pragma unroll
    for (int st = 0; st < 2; st++) {
        const int k0 = st * BKK;
        const uint32_t sa = sbase + st * STAGE_BYTES;
        const uint32_t sb = sa + STAGE_HALF;
        #pragma unroll
        for (int i = 0; i < 4; i++) {
            CP_ASYNC16(sa + so[i], gA[i] + k0);
            CP_ASYNC16(sb + so[i], gB[i] + k0);
        }
        CP_COMMIT();
    }

    int st = 0;
    for (int it = 0; it < NIT; it++) {
        CP_WAIT1();
        __syncthreads();

        if (it + 2 < NIT) {
            const int ps = (st + 2 >= NSTAGE) ? st + 2 - NSTAGE : st + 2;
            const int k0 = (it + 2) * BKK;
            const uint32_t sa = sbase + ps * STAGE_BYTES;
            const uint32_t sb = sa + STAGE_HALF;
            #pragma unroll
            for (int i = 0; i < 4; i++) {
                CP_ASYNC16(sa + so[i], gA[i] + k0);
                CP_ASYNC16(sb + so[i], gB[i] + k0);
            }
        }
        CP_COMMIT();

        const uint32_t sa = sbase + st * STAGE_BYTES;
        const uint32_t sb = sa + STAGE_HALF;
        #pragma unroll
        for (int ks = 0; ks < 4; ks++) {
            uint32_t a[4][4];
            #pragma unroll
            for (int mt = 0; mt < 4; mt++) {
                uint32_t ad = sa + aoff + mt * (16 * RSTR) + ks * 32;
                LDMATRIX_X4(a[mt][0], a[mt][1], a[mt][2], a[mt][3], ad);
            }
            uint32_t b[2][4];
            #pragma unroll
            for (int np = 0; np < 2; np++) {
                uint32_t bd = sb + boff + np * (16 * RSTR) + ks * 32;
                LDMATRIX_X4(b[np][0], b[np][1], b[np][2], b[np][3], bd);
            }
            #pragma unroll
            for (int mt = 0; mt < 4; mt++) {
                #pragma unroll
                for (int nt = 0; nt < 4; nt++) {
                    const int np = nt >> 1, no = nt & 1;
                    MMA_16816(acc[mt][nt][0], acc[mt][nt][1], acc[mt][nt][2], acc[mt][nt][3],
                              a[mt][0], a[mt][1], a[mt][2], a[mt][3],
                              b[np][no], b[np][2 + no]);
                }
            }
        }
        st = (st + 1 == NSTAGE) ? 0 : st + 1;
    }

    const int mrow = lid >> 2;
    const int mcol = (lid & 3) * 2;
    #pragma unroll
    for (int mt = 0; mt < 4; mt++) {
        #pragma unroll
        for (int nt = 0; nt < 4; nt++) {
            const int row = bm + wm + mt * 16 + mrow;
            const int col = bn + wn + nt * 8 + mcol;
            float2 v01 = make_float2(acc[mt][nt][0], acc[mt][nt][1]);
            float2 v23 = make_float2(acc[mt][nt][2], acc[mt][nt][3]);
            *(float2*)(g_logits + (size_t)row * K_DIM + col) = v01;
            *(float2*)(g_logits + (size_t)(row + 8) * K_DIM + col) = v23;
        }
    }
}

// ---------------- K2: column pass -------------------------------------------------
__global__ void __launch_bounds__(256) colpass_kernel() {
    const int k = blockIdx.x * 256 + threadIdx.x;
    const int bc = blockIdx.y;
    const int s = blockIdx.z;
    const float* __restrict__ base =
        g_logits + ((size_t)(s * B_DIM + bc * 1024)) * K_DIM + k;
    float m = -1e30f, sum = 0.f;
    for (int b0 = 0; b0 < 1024; b0 += 8) {
        float v[8];
        #pragma unroll
        for (int j = 0; j < 8; j++) v[j] = base[(size_t)(b0 + j) * K_DIM] * 20.0f;
        #pragma unroll
        for (int j = 0; j < 8; j++) {
            if (v[j] <= m) sum += fast_exp(v[j] - m);
            else { sum = fmaf(sum, fast_exp(m - v[j]), 1.0f); m = v[j]; }
        }
    }
    const int pidx = (bc * S_DIM + s) * K_DIM + k;
    g_part_m[pidx] = m;
    g_part_s[pidx] = sum;
}

__global__ void __launch_bounds__(256) combine1_kernel() {
    const int idx = blockIdx.x * 256 + threadIdx.x;
    const int s = idx >> 13, k = idx & (K_DIM - 1);
    float m = -1e30f;
    #pragma unroll
    for (int bc = 0; bc < 4; bc++)
        m = fmaxf(m, g_part_m[(bc * S_DIM + s) * K_DIM + k]);
    float A = 0.f;
    #pragma unroll
    for (int bc = 0; bc < 4; bc++) {
        const int pi = (bc * S_DIM + s) * K_DIM + k;
        A = fmaf(g_part_s[pi], fast_exp(g_part_m[pi] - m), A);
    }
    float A1 = 5.1847055285870724e21f * A;   // * exp(50)
    g_shift[idx] = m;
    g_c[idx] = 1.0f / (A1 + 1e-8f);
    g_A[idx] = 0.f;
}

__global__ void __launch_bounds__(256) update_c_kernel() {
    const int idx = blockIdx.x * 256 + threadIdx.x;
    float c = g_c[idx], A = g_A[idx];
    g_c[idx] = c / (c * A + 1e-8f);
    g_A[idx] = 0.f;
    if (idx == 0) g_loss = 0.f;
}

// ---------------- row passes (smem ebuf, 16 rows/CTA, high occupancy) -------------
// MODE 1: B1 -> r1, fused pred-LSE, fused A2 partials
// MODE 2: B2 -> r2, fused A3 partials
// MODE 3: B3 -> r3, write final assignments, fused loss
template <int MODE>
__global__ void __launch_bounds__(256) rowpass_kernel(float* __restrict__ outp) {
    __shared__ float seb[32 * 256];   // 32 KB staging for e / t values
    __shared__ float sA[8], sB[8], sC[8];
    __shared__ float bcast[1];
    const int tid = threadIdx.x;
    const int warp = tid >> 5, lane = tid & 31;
    const int r0 = blockIdx.x * RPC;
    const int s = r0 >> 12;
    const float* __restrict__ shiftv = g_shift + s * K_DIM;
    const float* __restrict__ cv = g_c + s * K_DIM;

    float accR[32];
    if (MODE != 3) {
        #pragma unroll
        for (int j = 0; j < 32; j++) accR[j] = 0.f;
    }
    float lossAcc = 0.f;

    for (int rr = 0; rr < RPC; rr++) {
        const int row = r0 + rr;
        const float* __restrict__ lrow = g_logits + (size_t)row * K_DIM;
        float sumB = 0.f, sumV = 0.f;
        float lm = -1e30f, ls = 0.f;
        #pragma unroll
        for (int j = 0; j < 32; j++) {
            const int k = tid + (j << 8);
            float l = lrow[k];
            float e = fast_exp(fmaf(l, 20.0f, 50.0f - shiftv[k]));
            float t = e * cv[k];
            sumB += t;
            if (MODE == 3) {
                seb[(j << 8) + tid] = t;
                sumV = fmaf(t, l * 8.3333333333333339f, sumV);
            } else {
                seb[(j << 8) + tid] = e;
            }
            if (MODE == 1) {
                float pp = l * 8.3333333333333339f;
                if (pp <= lm) ls += fast_exp(pp - lm);
                else { ls = fmaf(ls, fast_exp(lm - pp), 1.0f); lm = pp; }
            }
        }
        #pragma unroll
        for (int o = 16; o > 0; o >>= 1) {
            sumB += __shfl_xor_sync(0xffffffffu, sumB, o);
            if (MODE == 3) sumV += __shfl_xor_sync(0xffffffffu, sumV, o);
            if (MODE == 1) {
                float m2 = __shfl_xor_sync(0xffffffffu, lm, o);
                float s2 = __shfl_xor_sync(0xffffffffu, ls, o);
                float mm = fmaxf(lm, m2);
                ls = ls * fast_exp(lm - mm) + s2 * fast_exp(m2 - mm);
                lm = mm;
            }
        }
        if (lane == 0) {
            sA[warp] = sumB;
            if (MODE == 3) sB[warp] = sumV;
            if (MODE == 1) { sB[warp] = lm; sC[warp] = ls; }
        }
        __syncthreads();
        if (tid == 0) {
            float Bt = 0.f, Vt = 0.f, Mt = -1e30f, St = 0.f;
            #pragma unroll
            for (int w = 0; w < 8; w++) {
                Bt += sA[w];
                if (MODE == 3) Vt += sB[w];
                if (MODE == 1) {
                    float m2 = sB[w], s2 = sC[w];
                    float mm = fmaxf(Mt, m2);
                    St = St * fast_exp(Mt - mm) + s2 * fast_exp(m2 - mm);
                    Mt = mm;
                }
            }
            float rnew;
            if (MODE == 1) {
                rnew = 1.0f / (Bt + 1e-8f);
                g_r[row] = rnew;
                g_lse[row] = Mt + logf(St);
            } else {
                float rold = g_r[row];
                rnew = rold / (rold * Bt + 1e-8f);
                if (MODE == 2) g_r[row] = rnew;
                if (MODE == 3) lossAcc = fmaf(rnew, g_lse[row] * Bt - Vt, lossAcc);
            }
            bcast[0] = rnew;
        }
        __syncthreads();
        const float rnew = bcast[0];
        if (MODE == 3) {
            float* orow = outp + (size_t)row * K_DIM;
            #pragma unroll
            for (int j = 0; j < 32; j++) orow[tid + (j << 8)] = seb[(j << 8) + tid] * rnew;
        } else {
            #pragma unroll
            for (int j = 0; j < 32; j++)
                accR[j] = fmaf(seb[(j << 8) + tid], rnew, accR[j]);
        }
        __syncthreads();   // seb reused next row
    }

    if (MODE != 3) {
        float* Ag = g_A + s * K_DIM;
        #pragma unroll
        for (int j = 0; j < 32; j++) atomicAdd(&Ag[tid + (j << 8)], accR[j]);
    } else {
        if (tid == 0) atomicAdd(&g_loss, lossAcc);
    }
}

__global__ void finalize_kernel(float* dst) {
    dst[0] = g_loss * (1.0f / 16384.0f);
}

// ---------------- launch ----------------------------------------------------------
extern "C" void kernel_launch(void* const* d_in, const int* in_sizes, int n_in,
                              void* d_out, int out_size) {
    const float* x = (const float*)d_in[0];
    const float* W = (const float*)d_in[1];
    if (n_in >= 2 && in_sizes[0] == K_DIM * D_DIM && in_sizes[1] == N_ROWS * D_DIM) {
        const float* t = x; x = W; W = t;
    }
    float* out = (float*)d_out;

    float* outp = out;
    if ((long long)out_size < TOT_ELEMS) {
        void* p = nullptr;
        cudaGetSymbolAddress(&p, g_logits);
        outp = (float*)p;
    }

    void *pA3, *pB3;
    cudaGetSymbolAddress(&pA3, g_A3);
    cudaGetSymbolAddress(&pB3, g_B3);

    cudaFuncSetAttribute(gemm_hmma, cudaFuncAttributeMaxDynamicSharedMemorySize, GEMM_SMEM);

    norm_kernel<<<N_ROWS / 8, 256>>>(x);
    convA_kernel<<<(N_ROWS * (D_DIM / 2)) / 256, 256>>>(x);
    convB_kernel<<<(K_DIM * (D_DIM / 2)) / 256, 256>>>(W);

    gemm_hmma<<<dim3(K_DIM / BN, N_ROWS / BM), 256, GEMM_SMEM>>>(
        (const __nv_bfloat16*)pA3, (const __nv_bfloat16*)pB3);

    colpass_kernel<<<dim3(K_DIM / 256, 4, S_DIM), 256>>>();
    combine1_kernel<<<(S_DIM * K_DIM) / 256, 256>>>();

    rowpass_kernel<1><<<N_ROWS / RPC, 256>>>(nullptr);
    update_c_kernel<<<(S_DIM * K_DIM) / 256, 256>>>();
    rowpass_kernel<2><<<N_ROWS / RPC, 256>>>(nullptr);
    update_c_kernel<<<(S_DIM * K_DIM) / 256, 256>>>();
    rowpass_kernel<3><<<N_ROWS / RPC, 256>>>(outp);

    if ((long long)out_size > TOT_ELEMS) {
        finalize_kernel<<<1, 1>>>(out + TOT_ELEMS);
    } else if (out_size == 1) {
        finalize_kernel<<<1, 1>>>(out);
    }
}